// round 13
// baseline (speedup 1.0000x reference)
#include <cuda_runtime.h>
#include <cstdint>
#include <cstddef>

// Single fused kernel, one launch. Phase 1: each block cooperatively builds the
// Wigner D matrices (D1: 16x3x3, D2: 16x5x5) into shared memory — warp w
// handles t = 4w..4w+3, lane = matrix entry (i,j). Chain Za@J@Zb@J@Zg computed
// as A=J@Zb (sparse col-combine), B=A@J (dense), C=Za@B (sparse row-combine),
// D=C@Zg (sparse col-combine). Z-rot sparsity: row i has cos(f_i) at (i,i) and
// sin(f_i) at (i,rev_i), f_i = l-i (center row degenerates correctly).
// Phase 2: the R4-proven transform body, one block per 4 points, grid N/4,
// independent blocks (no persistence, no cache hints).
__global__ __launch_bounds__(128) void fused_kernel(
        const float* __restrict__ feat,
        const float* __restrict__ q,
        const float* __restrict__ J1,
        const float* __restrict__ J2,
        float* __restrict__ out,
        int N, int T) {
    __shared__ float sStage[2816];   // stage buf0 [0,1408), buf1 [1408,2816);
                                     // sF aliases [0,1920); build scratch [1920,2368)
    __shared__ float sD1[144];
    __shared__ float sD2[400];

    const int tid = threadIdx.x;
    const int lane = tid & 31;
    const int warp = tid >> 5;
    const int pbase = blockIdx.x * 4;

    // ---------------- Phase 1: cooperative D build (R9-verified) ----------------
    {
        float* scrA = sStage + 1920 + warp * 112;
        float* scrB = scrA + 56;
        const int i5 = lane / 5, j5 = lane % 5;
        const int i3 = lane / 3, j3 = lane % 3;

        for (int s = 0; s < 4; s++) {
            const int t = 4 * warp + s;
            if (t >= T) break;
            float qr = __ldg(q + 4 * t + 0), qi = __ldg(q + 4 * t + 1);
            float qj = __ldg(q + 4 * t + 2), qk = __ldg(q + 4 * t + 3);
            float inv = rsqrtf(qr * qr + qi * qi + qj * qj + qk * qk);
            qr *= inv; qi *= inv; qj *= inv; qk *= inv;
            float two_s = 2.0f / (qr * qr + qi * qi + qj * qj + qk * qk);
            float M01 = two_s * (qi * qj - qk * qr);
            float M21 = two_s * (qj * qk + qi * qr);
            float M11 = 1.0f - two_s * (qi * qi + qk * qk);
            float M10 = two_s * (qi * qj + qk * qr);
            float M12 = two_s * (qj * qk - qi * qr);
            float alpha = atan2f(M01, M21);
            float beta  = acosf(fmaxf(-1.0f, fminf(1.0f, M11)));
            float gamma = atan2f(M10, -M12);

            // ---- D2 (5x5), lanes 0..24 ----
            if (lane < 25) {      // A = J2 @ Zb(beta): col-combine
                float fj = (float)(2 - j5);
                scrA[i5 * 5 + j5] =
                    __ldg(J2 + i5 * 5 + j5) * cosf(fj * beta) +
                    __ldg(J2 + i5 * 5 + (4 - j5)) * sinf(-fj * beta);
            }
            __syncwarp();
            if (lane < 25) {      // B = A @ J2: dense
                float B = 0.0f;
#pragma unroll
                for (int k = 0; k < 5; k++)
                    B = fmaf(scrA[i5 * 5 + k], __ldg(J2 + k * 5 + j5), B);
                scrB[i5 * 5 + j5] = B;
            }
            __syncwarp();
            if (lane < 25) {      // C = Za(alpha) @ B: row-combine
                float fi = (float)(2 - i5);
                scrA[i5 * 5 + j5] =
                    cosf(fi * alpha) * scrB[i5 * 5 + j5] +
                    sinf(fi * alpha) * scrB[(4 - i5) * 5 + j5];
            }
            __syncwarp();
            if (lane < 25) {      // D = C @ Zg(gamma): col-combine
                float fj = (float)(2 - j5);
                sD2[t * 25 + lane] =
                    scrA[i5 * 5 + j5] * cosf(fj * gamma) +
                    scrA[i5 * 5 + (4 - j5)] * sinf(-fj * gamma);
            }
            __syncwarp();

            // ---- D1 (3x3), lanes 0..8 (reuse scratch) ----
            if (lane < 9) {
                float fj = (float)(1 - j3);
                scrA[i3 * 3 + j3] =
                    __ldg(J1 + i3 * 3 + j3) * cosf(fj * beta) +
                    __ldg(J1 + i3 * 3 + (2 - j3)) * sinf(-fj * beta);
            }
            __syncwarp();
            if (lane < 9) {
                float B = 0.0f;
#pragma unroll
                for (int k = 0; k < 3; k++)
                    B = fmaf(scrA[i3 * 3 + k], __ldg(J1 + k * 3 + j3), B);
                scrB[i3 * 3 + j3] = B;
            }
            __syncwarp();
            if (lane < 9) {
                float fi = (float)(1 - i3);
                scrA[i3 * 3 + j3] =
                    cosf(fi * alpha) * scrB[i3 * 3 + j3] +
                    sinf(fi * alpha) * scrB[(2 - i3) * 3 + j3];
            }
            __syncwarp();
            if (lane < 9) {
                float fj = (float)(1 - j3);
                sD1[t * 9 + lane] =
                    scrA[i3 * 3 + j3] * cosf(fj * gamma) +
                    scrA[i3 * 3 + (2 - j3)] * sinf(-fj * gamma);
            }
            __syncwarp();
        }
    }
    __syncthreads();   // sD1/sD2 + scratch done before sF overwrite

    // ---------------- Phase 2: R4-proven transform body ----------------
    float* sF = sStage;
    {
        const float4* src = reinterpret_cast<const float4*>(feat + (size_t)pbase * 480);
        float4* dst = reinterpret_cast<float4*>(sF);
        for (int x = tid; x < 480; x += 128) dst[x] = src[x];
    }
    __syncthreads();

    // Register gather (all indices compile-time after unrolling).
    float4 f0[4];
    float in1[4][3];
    float in2[4][5];
    if (tid < 32) {
#pragma unroll
        for (int pp = 0; pp < 4; pp++)
            f0[pp] = reinterpret_cast<const float4*>(sF + pp * 480)[tid];
    } else if (tid < 96) {
        const int m = tid - 32;
#pragma unroll
        for (int pp = 0; pp < 4; pp++)
#pragma unroll
            for (int b = 0; b < 3; b++)
                in1[pp][b] = sF[pp * 480 + 128 + 3 * m + b];
    } else {
        const int m = tid - 96;
#pragma unroll
        for (int pp = 0; pp < 4; pp++)
#pragma unroll
            for (int b = 0; b < 5; b++)
                in2[pp][b] = sF[pp * 480 + 320 + 5 * m + b];
    }
    __syncthreads();   // done reading sF before first stage write

    for (int t = 0; t < T; t++) {
        float* buf = sStage + (t & 1) * 1408;

        if (tid >= 32 && tid < 96) {
            const int m = tid - 32;
            const float* D = sD1 + t * 9;
#pragma unroll
            for (int a = 0; a < 3; a++) {
                const float d0 = D[a * 3 + 0];
                const float d1 = D[a * 3 + 1];
                const float d2 = D[a * 3 + 2];
#pragma unroll
                for (int pp = 0; pp < 4; pp++)
                    buf[pp * 352 + 3 * m + a] =
                        fmaf(d0, in1[pp][0], fmaf(d1, in1[pp][1], d2 * in1[pp][2]));
            }
        } else if (tid >= 96) {
            const int m = tid - 96;
            const float* D = sD2 + t * 25;
#pragma unroll
            for (int a = 0; a < 5; a++) {
                const float d0 = D[a * 5 + 0];
                const float d1 = D[a * 5 + 1];
                const float d2 = D[a * 5 + 2];
                const float d3 = D[a * 5 + 3];
                const float d4 = D[a * 5 + 4];
#pragma unroll
                for (int pp = 0; pp < 4; pp++) {
                    float s = d0 * in2[pp][0];
                    s = fmaf(d1, in2[pp][1], s);
                    s = fmaf(d2, in2[pp][2], s);
                    s = fmaf(d3, in2[pp][3], s);
                    s = fmaf(d4, in2[pp][4], s);
                    buf[pp * 352 + 192 + 5 * m + a] = s;
                }
            }
        }
        __syncthreads();
        // Single barrier per t is safe with double buffering: a thread reaches
        // the stage-write of iter t+2 (same buffer as t) only after passing the
        // barrier of iter t+1, which requires ALL threads to have finished
        // their iter-t copy-out.

        float* obase = out + ((size_t)t * N + pbase) * 480;
        if (tid < 32) {
#pragma unroll
            for (int pp = 0; pp < 4; pp++)
                reinterpret_cast<float4*>(obase + pp * 480)[tid] = f0[pp];
        } else {
            // 352 staged float4 chunks distributed over 96 threads.
            for (int x = tid - 32; x < 352; x += 96) {
                const int pp = x / 88;
                const int c4 = x - pp * 88;
                float4 v = reinterpret_cast<const float4*>(buf + pp * 352)[c4];
                reinterpret_cast<float4*>(obase + pp * 480 + 128)[c4] = v;
            }
        }
    }
}

extern "C" void kernel_launch(void* const* d_in, const int* in_sizes, int n_in,
                              void* d_out, int out_size) {
    const float* feat = (const float*)d_in[0];
    const float* q    = (const float*)d_in[1];
    // d_in[2] = J0 (unused: l=0 is a pure broadcast in the reference)
    const float* J1   = (const float*)d_in[3];
    const float* J2   = (const float*)d_in[4];
    float* out = (float*)d_out;

    const int T = in_sizes[1] / 4;     // 16
    const int N = in_sizes[0] / 480;   // 16384

    fused_kernel<<<N / 4, 128>>>(feat, q, J1, J2, out, N, T);
}

// round 15
// speedup vs baseline: 1.1250x; 1.1250x over previous
#include <cuda_runtime.h>
#include <cstdint>
#include <cstddef>

// Single fused kernel, one launch.
// Phase 1 (cheap build): each warp builds D for quats t=4w..4w+3.
//  (a) Lane-parallel transcendentals: lanes split 8-per-quat; within a group,
//      lane k=0 computes alpha (atan2), k=1 beta (acos), k=2 gamma (atan2),
//      then ONE sincosf each; double-angle gives the full freq table
//      {cos(f a), sin(f a), f=2..-2}, written straight to a per-warp smem
//      table (no selects, no per-element trig).
//  (b) Stage chain per quat (validated in R12, same signs): A=J2@Zb (sparse
//      col-combine), B=A@J2 (dense), C=Za@B (sparse row-combine),
//      D=C@Zg (sparse col-combine); 3x3 uses the same tables at index+1.
// Phase 2: R4-proven transform body (one block per 4 points, grid N/4).
__global__ __launch_bounds__(128) void fused_kernel(
        const float* __restrict__ feat,
        const float* __restrict__ q,
        const float* __restrict__ J1,
        const float* __restrict__ J2,
        float* __restrict__ out,
        int N, int T) {
    __shared__ float sStage[2816];   // stage buf0 [0,1408), buf1 [1408,2816);
                                     // sF aliases [0,1920); build scratch [0,768)
    __shared__ float sD1[144];
    __shared__ float sD2[400];

    const int tid = threadIdx.x;
    const int lane = tid & 31;
    const int warp = tid >> 5;
    const int pbase = blockIdx.x * 4;

    // ---------------- Phase 1: cheap cooperative D build ----------------
    {
        float* wscr = sStage + warp * 192;   // tables 4x32 [0,128), scrA@128, scrB@160
        const int t0 = 4 * warp;

        // (a) transcendentals + trig tables, all 4 quats of this warp in parallel
        {
            const int sg = lane >> 3;        // quat group 0..3
            const int k  = lane & 7;
            const int t  = t0 + sg;
            if (t < T && k < 3) {
                float qr = __ldg(q + 4 * t + 0), qi = __ldg(q + 4 * t + 1);
                float qj = __ldg(q + 4 * t + 2), qk = __ldg(q + 4 * t + 3);
                float inv = rsqrtf(qr * qr + qi * qi + qj * qj + qk * qk);
                qr *= inv; qi *= inv; qj *= inv; qk *= inv;
                float two_s = 2.0f / (qr * qr + qi * qi + qj * qj + qk * qk);
                float M01 = two_s * (qi * qj - qk * qr);
                float M21 = two_s * (qj * qk + qi * qr);
                float M11 = 1.0f - two_s * (qi * qi + qk * qk);
                float M10 = two_s * (qi * qj + qk * qr);
                float M12 = two_s * (qj * qk - qi * qr);

                float ang;
                if (k == 1) {
                    ang = acosf(fmaxf(-1.0f, fminf(1.0f, M11)));      // beta
                } else {
                    float y = (k == 0) ? M01 : M10;
                    float x = (k == 0) ? M21 : -M12;
                    ang = atan2f(y, x);                               // alpha / gamma
                }
                float s1, c1;
                sincosf(ang, &s1, &c1);
                float c2 = fmaf(2.0f * c1, c1, -1.0f);
                float s2 = 2.0f * s1 * c1;

                // table block for this angle: [c(2a),c(a),1,c(a),c(2a) | s(2a),s(a),0,-s(a),-s(2a)]
                float* tb = wscr + sg * 32 + k * 10;   // k=0:alpha, 1:beta, 2:gamma
                tb[0] = c2; tb[1] = c1; tb[2] = 1.0f; tb[3] = c1; tb[4] = c2;
                tb[5] = s2; tb[6] = s1; tb[7] = 0.0f; tb[8] = -s1; tb[9] = -s2;
            }
        }
        __syncwarp();

        // (b) stage chain, quat-sequential, lane = matrix entry
        float* scrA = wscr + 128;
        float* scrB = wscr + 160;
        const int i5 = lane / 5, j5 = lane % 5;
        const int i3 = lane / 3, j3 = lane % 3;

        for (int s = 0; s < 4; s++) {
            const int t = t0 + s;
            if (t >= T) break;
            const float* tab = wscr + s * 32;   // [cA5 sA5 cB5 sB5 cG5 sG5]

            // ---- D2 (5x5), lanes 0..24 ----
            if (lane < 25)      // A = J2 @ Zb
                scrA[i5 * 5 + j5] =
                    __ldg(J2 + i5 * 5 + j5) * tab[10 + j5] -
                    __ldg(J2 + i5 * 5 + (4 - j5)) * tab[15 + j5];
            __syncwarp();
            if (lane < 25) {    // B = A @ J2
                float B = 0.0f;
#pragma unroll
                for (int k = 0; k < 5; k++)
                    B = fmaf(scrA[i5 * 5 + k], __ldg(J2 + k * 5 + j5), B);
                scrB[i5 * 5 + j5] = B;
            }
            __syncwarp();
            if (lane < 25)      // C = Za @ B
                scrA[i5 * 5 + j5] =
                    tab[i5] * scrB[i5 * 5 + j5] +
                    tab[5 + i5] * scrB[(4 - i5) * 5 + j5];
            __syncwarp();
            if (lane < 25)      // D = C @ Zg
                sD2[t * 25 + lane] =
                    scrA[i5 * 5 + j5] * tab[20 + j5] -
                    scrA[i5 * 5 + (4 - j5)] * tab[25 + j5];
            __syncwarp();

            // ---- D1 (3x3), lanes 0..8; 3-dim freq f=1-j -> table index j+1 ----
            if (lane < 9)
                scrA[i3 * 3 + j3] =
                    __ldg(J1 + i3 * 3 + j3) * tab[10 + j3 + 1] -
                    __ldg(J1 + i3 * 3 + (2 - j3)) * tab[15 + j3 + 1];
            __syncwarp();
            if (lane < 9) {
                float B = 0.0f;
#pragma unroll
                for (int k = 0; k < 3; k++)
                    B = fmaf(scrA[i3 * 3 + k], __ldg(J1 + k * 3 + j3), B);
                scrB[i3 * 3 + j3] = B;
            }
            __syncwarp();
            if (lane < 9)
                scrA[i3 * 3 + j3] =
                    tab[i3 + 1] * scrB[i3 * 3 + j3] +
                    tab[5 + i3 + 1] * scrB[(2 - i3) * 3 + j3];
            __syncwarp();
            if (lane < 9)
                sD1[t * 9 + lane] =
                    scrA[i3 * 3 + j3] * tab[20 + j3 + 1] -
                    scrA[i3 * 3 + (2 - j3)] * tab[25 + j3 + 1];
            __syncwarp();
        }
    }
    __syncthreads();   // sD1/sD2 + scratch done before sF overwrite

    // ---------------- Phase 2: R4-proven transform body ----------------
    float* sF = sStage;
    {
        const float4* src = reinterpret_cast<const float4*>(feat + (size_t)pbase * 480);
        float4* dst = reinterpret_cast<float4*>(sF);
        for (int x = tid; x < 480; x += 128) dst[x] = src[x];
    }
    __syncthreads();

    // Register gather (all indices compile-time after unrolling).
    float4 f0[4];
    float in1[4][3];
    float in2[4][5];
    if (tid < 32) {
#pragma unroll
        for (int pp = 0; pp < 4; pp++)
            f0[pp] = reinterpret_cast<const float4*>(sF + pp * 480)[tid];
    } else if (tid < 96) {
        const int m = tid - 32;
#pragma unroll
        for (int pp = 0; pp < 4; pp++)
#pragma unroll
            for (int b = 0; b < 3; b++)
                in1[pp][b] = sF[pp * 480 + 128 + 3 * m + b];
    } else {
        const int m = tid - 96;
#pragma unroll
        for (int pp = 0; pp < 4; pp++)
#pragma unroll
            for (int b = 0; b < 5; b++)
                in2[pp][b] = sF[pp * 480 + 320 + 5 * m + b];
    }
    __syncthreads();   // done reading sF before first stage write

    for (int t = 0; t < T; t++) {
        float* buf = sStage + (t & 1) * 1408;

        if (tid >= 32 && tid < 96) {
            const int m = tid - 32;
            const float* D = sD1 + t * 9;
#pragma unroll
            for (int a = 0; a < 3; a++) {
                const float d0 = D[a * 3 + 0];
                const float d1 = D[a * 3 + 1];
                const float d2 = D[a * 3 + 2];
#pragma unroll
                for (int pp = 0; pp < 4; pp++)
                    buf[pp * 352 + 3 * m + a] =
                        fmaf(d0, in1[pp][0], fmaf(d1, in1[pp][1], d2 * in1[pp][2]));
            }
        } else if (tid >= 96) {
            const int m = tid - 96;
            const float* D = sD2 + t * 25;
#pragma unroll
            for (int a = 0; a < 5; a++) {
                const float d0 = D[a * 5 + 0];
                const float d1 = D[a * 5 + 1];
                const float d2 = D[a * 5 + 2];
                const float d3 = D[a * 5 + 3];
                const float d4 = D[a * 5 + 4];
#pragma unroll
                for (int pp = 0; pp < 4; pp++) {
                    float s = d0 * in2[pp][0];
                    s = fmaf(d1, in2[pp][1], s);
                    s = fmaf(d2, in2[pp][2], s);
                    s = fmaf(d3, in2[pp][3], s);
                    s = fmaf(d4, in2[pp][4], s);
                    buf[pp * 352 + 192 + 5 * m + a] = s;
                }
            }
        }
        __syncthreads();
        // Single barrier per t is safe with double buffering: a thread reaches
        // the stage-write of iter t+2 (same buffer as t) only after passing the
        // barrier of iter t+1, which requires ALL threads to have finished
        // their iter-t copy-out.

        float* obase = out + ((size_t)t * N + pbase) * 480;
        if (tid < 32) {
#pragma unroll
            for (int pp = 0; pp < 4; pp++)
                reinterpret_cast<float4*>(obase + pp * 480)[tid] = f0[pp];
        } else {
            // 352 staged float4 chunks distributed over 96 threads.
            for (int x = tid - 32; x < 352; x += 96) {
                const int pp = x / 88;
                const int c4 = x - pp * 88;
                float4 v = reinterpret_cast<const float4*>(buf + pp * 352)[c4];
                reinterpret_cast<float4*>(obase + pp * 480 + 128)[c4] = v;
            }
        }
    }
}

extern "C" void kernel_launch(void* const* d_in, const int* in_sizes, int n_in,
                              void* d_out, int out_size) {
    const float* feat = (const float*)d_in[0];
    const float* q    = (const float*)d_in[1];
    // d_in[2] = J0 (unused: l=0 is a pure broadcast in the reference)
    const float* J1   = (const float*)d_in[3];
    const float* J2   = (const float*)d_in[4];
    float* out = (float*)d_out;

    const int T = in_sizes[1] / 4;     // 16
    const int N = in_sizes[0] / 480;   // 16384

    fused_kernel<<<N / 4, 128>>>(feat, q, J1, J2, out, N, T);
}

// round 16
// speedup vs baseline: 1.1937x; 1.0611x over previous
#include <cuda_runtime.h>
#include <cstdint>
#include <cstddef>

// Single fused kernel, one launch.
// Phase 0: prefetch this block's 4 points of features into REGISTERS (LDG in
//          flight during the build — overlaps global latency with compute).
// Phase 1 (cheap build, R14-validated): each warp builds D for quats
//          t=4w..4w+3 via lane-parallel transcendentals (one sincosf per angle,
//          double-angle fills the freq table) + sparse stage chain
//          A=J@Zb, B=A@J, C=Za@B, D=C@Zg in dedicated smem scratch.
// Phase 2: R4-proven transform body (one block per 4 points, grid N/4).
__global__ __launch_bounds__(128) void fused_kernel(
        const float* __restrict__ feat,
        const float* __restrict__ q,
        const float* __restrict__ J1,
        const float* __restrict__ J2,
        float* __restrict__ out,
        int N, int T) {
    __shared__ float sStage[2816];   // stage buf0 [0,1408), buf1 [1408,2816); sF aliases [0,1920)
    __shared__ float sScr[768];      // dedicated build scratch: 4 warps x 192
    __shared__ float sD1[144];
    __shared__ float sD2[400];

    const int tid = threadIdx.x;
    const int lane = tid & 31;
    const int warp = tid >> 5;
    const int pbase = blockIdx.x * 4;

    // ---------------- Phase 0: feature prefetch into registers ----------------
    float4 pre[4];
    int npre = 0;
    {
        const float4* src = reinterpret_cast<const float4*>(feat + (size_t)pbase * 480);
#pragma unroll
        for (int it = 0; it < 4; it++) {
            int x = tid + it * 128;
            if (x < 480) { pre[it] = src[x]; npre = it + 1; }
        }
    }

    // ---------------- Phase 1: cheap cooperative D build ----------------
    {
        float* wscr = sScr + warp * 192;   // tables 4x32 [0,128), scrA@128, scrB@160
        const int t0 = 4 * warp;

        // (a) transcendentals + trig tables, 4 quats of this warp in parallel
        {
            const int sg = lane >> 3;        // quat group 0..3
            const int k  = lane & 7;
            const int t  = t0 + sg;
            if (t < T && k < 3) {
                float qr = __ldg(q + 4 * t + 0), qi = __ldg(q + 4 * t + 1);
                float qj = __ldg(q + 4 * t + 2), qk = __ldg(q + 4 * t + 3);
                float inv = rsqrtf(qr * qr + qi * qi + qj * qj + qk * qk);
                qr *= inv; qi *= inv; qj *= inv; qk *= inv;
                float two_s = 2.0f / (qr * qr + qi * qi + qj * qj + qk * qk);
                float M01 = two_s * (qi * qj - qk * qr);
                float M21 = two_s * (qj * qk + qi * qr);
                float M11 = 1.0f - two_s * (qi * qi + qk * qk);
                float M10 = two_s * (qi * qj + qk * qr);
                float M12 = two_s * (qj * qk - qi * qr);

                float ang;
                if (k == 1) {
                    ang = acosf(fmaxf(-1.0f, fminf(1.0f, M11)));      // beta
                } else {
                    float y = (k == 0) ? M01 : M10;
                    float x = (k == 0) ? M21 : -M12;
                    ang = atan2f(y, x);                               // alpha / gamma
                }
                float s1, c1;
                sincosf(ang, &s1, &c1);
                float c2 = fmaf(2.0f * c1, c1, -1.0f);
                float s2 = 2.0f * s1 * c1;

                // [c(2a),c(a),1,c(a),c(2a) | s(2a),s(a),0,-s(a),-s(2a)]
                float* tb = wscr + sg * 32 + k * 10;   // k=0:alpha, 1:beta, 2:gamma
                tb[0] = c2; tb[1] = c1; tb[2] = 1.0f; tb[3] = c1; tb[4] = c2;
                tb[5] = s2; tb[6] = s1; tb[7] = 0.0f; tb[8] = -s1; tb[9] = -s2;
            }
        }
        __syncwarp();

        // (b) stage chain, quat-sequential, lane = matrix entry
        float* scrA = wscr + 128;
        float* scrB = wscr + 160;
        const int i5 = lane / 5, j5 = lane % 5;
        const int i3 = lane / 3, j3 = lane % 3;

        for (int s = 0; s < 4; s++) {
            const int t = t0 + s;
            if (t >= T) break;
            const float* tab = wscr + s * 32;   // [cA5 sA5 cB5 sB5 cG5 sG5]

            // ---- D2 (5x5), lanes 0..24 ----
            if (lane < 25)      // A = J2 @ Zb
                scrA[i5 * 5 + j5] =
                    __ldg(J2 + i5 * 5 + j5) * tab[10 + j5] -
                    __ldg(J2 + i5 * 5 + (4 - j5)) * tab[15 + j5];
            __syncwarp();
            if (lane < 25) {    // B = A @ J2
                float B = 0.0f;
#pragma unroll
                for (int k = 0; k < 5; k++)
                    B = fmaf(scrA[i5 * 5 + k], __ldg(J2 + k * 5 + j5), B);
                scrB[i5 * 5 + j5] = B;
            }
            __syncwarp();
            if (lane < 25)      // C = Za @ B
                scrA[i5 * 5 + j5] =
                    tab[i5] * scrB[i5 * 5 + j5] +
                    tab[5 + i5] * scrB[(4 - i5) * 5 + j5];
            __syncwarp();
            if (lane < 25)      // D = C @ Zg
                sD2[t * 25 + lane] =
                    scrA[i5 * 5 + j5] * tab[20 + j5] -
                    scrA[i5 * 5 + (4 - j5)] * tab[25 + j5];
            __syncwarp();

            // ---- D1 (3x3), lanes 0..8; 3-dim freq f=1-j -> table index j+1 ----
            if (lane < 9)
                scrA[i3 * 3 + j3] =
                    __ldg(J1 + i3 * 3 + j3) * tab[10 + j3 + 1] -
                    __ldg(J1 + i3 * 3 + (2 - j3)) * tab[15 + j3 + 1];
            __syncwarp();
            if (lane < 9) {
                float B = 0.0f;
#pragma unroll
                for (int k = 0; k < 3; k++)
                    B = fmaf(scrA[i3 * 3 + k], __ldg(J1 + k * 3 + j3), B);
                scrB[i3 * 3 + j3] = B;
            }
            __syncwarp();
            if (lane < 9)
                scrA[i3 * 3 + j3] =
                    tab[i3 + 1] * scrB[i3 * 3 + j3] +
                    tab[5 + i3 + 1] * scrB[(2 - i3) * 3 + j3];
            __syncwarp();
            if (lane < 9)
                sD1[t * 9 + lane] =
                    scrA[i3 * 3 + j3] * tab[20 + j3 + 1] -
                    scrA[i3 * 3 + (2 - j3)] * tab[25 + j3 + 1];
            __syncwarp();
        }
    }

    // ---------------- Phase 2: R4-proven transform body ----------------
    // Dump prefetched features to smem (loads have had the whole build to land).
    float* sF = sStage;
    {
        float4* dst = reinterpret_cast<float4*>(sF);
#pragma unroll
        for (int it = 0; it < 4; it++)
            if (it < npre) dst[tid + it * 128] = pre[it];
    }
    __syncthreads();

    // Register gather (all indices compile-time after unrolling).
    float4 f0[4];
    float in1[4][3];
    float in2[4][5];
    if (tid < 32) {
#pragma unroll
        for (int pp = 0; pp < 4; pp++)
            f0[pp] = reinterpret_cast<const float4*>(sF + pp * 480)[tid];
    } else if (tid < 96) {
        const int m = tid - 32;
#pragma unroll
        for (int pp = 0; pp < 4; pp++)
#pragma unroll
            for (int b = 0; b < 3; b++)
                in1[pp][b] = sF[pp * 480 + 128 + 3 * m + b];
    } else {
        const int m = tid - 96;
#pragma unroll
        for (int pp = 0; pp < 4; pp++)
#pragma unroll
            for (int b = 0; b < 5; b++)
                in2[pp][b] = sF[pp * 480 + 320 + 5 * m + b];
    }
    __syncthreads();   // done reading sF before first stage write

    for (int t = 0; t < T; t++) {
        float* buf = sStage + (t & 1) * 1408;

        if (tid >= 32 && tid < 96) {
            const int m = tid - 32;
            const float* D = sD1 + t * 9;
#pragma unroll
            for (int a = 0; a < 3; a++) {
                const float d0 = D[a * 3 + 0];
                const float d1 = D[a * 3 + 1];
                const float d2 = D[a * 3 + 2];
#pragma unroll
                for (int pp = 0; pp < 4; pp++)
                    buf[pp * 352 + 3 * m + a] =
                        fmaf(d0, in1[pp][0], fmaf(d1, in1[pp][1], d2 * in1[pp][2]));
            }
        } else if (tid >= 96) {
            const int m = tid - 96;
            const float* D = sD2 + t * 25;
#pragma unroll
            for (int a = 0; a < 5; a++) {
                const float d0 = D[a * 5 + 0];
                const float d1 = D[a * 5 + 1];
                const float d2 = D[a * 5 + 2];
                const float d3 = D[a * 5 + 3];
                const float d4 = D[a * 5 + 4];
#pragma unroll
                for (int pp = 0; pp < 4; pp++) {
                    float s = d0 * in2[pp][0];
                    s = fmaf(d1, in2[pp][1], s);
                    s = fmaf(d2, in2[pp][2], s);
                    s = fmaf(d3, in2[pp][3], s);
                    s = fmaf(d4, in2[pp][4], s);
                    buf[pp * 352 + 192 + 5 * m + a] = s;
                }
            }
        }
        __syncthreads();
        // Single barrier per t is safe with double buffering: a thread reaches
        // the stage-write of iter t+2 (same buffer as t) only after passing the
        // barrier of iter t+1, which requires ALL threads to have finished
        // their iter-t copy-out.

        float* obase = out + ((size_t)t * N + pbase) * 480;
        if (tid < 32) {
#pragma unroll
            for (int pp = 0; pp < 4; pp++)
                reinterpret_cast<float4*>(obase + pp * 480)[tid] = f0[pp];
        } else {
            // 352 staged float4 chunks distributed over 96 threads.
            for (int x = tid - 32; x < 352; x += 96) {
                const int pp = x / 88;
                const int c4 = x - pp * 88;
                float4 v = reinterpret_cast<const float4*>(buf + pp * 352)[c4];
                reinterpret_cast<float4*>(obase + pp * 480 + 128)[c4] = v;
            }
        }
    }
}

extern "C" void kernel_launch(void* const* d_in, const int* in_sizes, int n_in,
                              void* d_out, int out_size) {
    const float* feat = (const float*)d_in[0];
    const float* q    = (const float*)d_in[1];
    // d_in[2] = J0 (unused: l=0 is a pure broadcast in the reference)
    const float* J1   = (const float*)d_in[3];
    const float* J2   = (const float*)d_in[4];
    float* out = (float*)d_out;

    const int T = in_sizes[1] / 4;     // 16
    const int N = in_sizes[0] / 480;   // 16384

    fused_kernel<<<N / 4, 128>>>(feat, q, J1, J2, out, N, T);
}